// round 1
// baseline (speedup 1.0000x reference)
#include <cuda_runtime.h>
#include <stdint.h>
#include <math.h>

#define TB 256

// ---------------------------------------------------------------------------
// Threefry-2x32, 20 rounds — bit-exact match of jax._src.prng.threefry2x32.
// ---------------------------------------------------------------------------
static __device__ __forceinline__ uint32_t rotl32(uint32_t x, uint32_t r) {
    return __funnelshift_l(x, x, r);
}

static __device__ __forceinline__ void tf2x32(uint32_t k0, uint32_t k1,
                                              uint32_t x0, uint32_t x1,
                                              uint32_t &o0, uint32_t &o1) {
    const uint32_t k2 = k0 ^ k1 ^ 0x1BD11BDAu;
    x0 += k0; x1 += k1;

    x0 += x1; x1 = rotl32(x1, 13); x1 ^= x0;
    x0 += x1; x1 = rotl32(x1, 15); x1 ^= x0;
    x0 += x1; x1 = rotl32(x1, 26); x1 ^= x0;
    x0 += x1; x1 = rotl32(x1,  6); x1 ^= x0;
    x0 += k1; x1 += k2 + 1u;

    x0 += x1; x1 = rotl32(x1, 17); x1 ^= x0;
    x0 += x1; x1 = rotl32(x1, 29); x1 ^= x0;
    x0 += x1; x1 = rotl32(x1, 16); x1 ^= x0;
    x0 += x1; x1 = rotl32(x1, 24); x1 ^= x0;
    x0 += k2; x1 += k0 + 2u;

    x0 += x1; x1 = rotl32(x1, 13); x1 ^= x0;
    x0 += x1; x1 = rotl32(x1, 15); x1 ^= x0;
    x0 += x1; x1 = rotl32(x1, 26); x1 ^= x0;
    x0 += x1; x1 = rotl32(x1,  6); x1 ^= x0;
    x0 += k0; x1 += k1 + 3u;

    x0 += x1; x1 = rotl32(x1, 17); x1 ^= x0;
    x0 += x1; x1 = rotl32(x1, 29); x1 ^= x0;
    x0 += x1; x1 = rotl32(x1, 16); x1 ^= x0;
    x0 += x1; x1 = rotl32(x1, 24); x1 ^= x0;
    x0 += k1; x1 += k2 + 4u;

    x0 += x1; x1 = rotl32(x1, 13); x1 ^= x0;
    x0 += x1; x1 = rotl32(x1, 15); x1 ^= x0;
    x0 += x1; x1 = rotl32(x1, 26); x1 ^= x0;
    x0 += x1; x1 = rotl32(x1,  6); x1 ^= x0;
    o0 = x0 + k2;
    o1 = x1 + k0 + 5u;
}

// bits -> N(0,1), matching jax.random.normal: u = uniform(lo=nextafter(-1,0), hi=1)
// from the top-23 mantissa trick, then sqrt(2)*erfinv(u).
static __device__ __forceinline__ float bits_to_normal(uint32_t bits) {
    float f  = __uint_as_float((bits >> 9) | 0x3f800000u) - 1.0f;  // [0,1)
    const float lo = -0.99999994f;                                  // nextafter(-1,0)
    float u = fmaxf(lo, f * 2.0f + lo);                             // hi-lo rounds to 2.0f
    return 1.41421356237309515f * erfinvf(u);
}

static __device__ __forceinline__ float elu_f(float z) {
    return (z > 0.0f) ? z : (__expf(z) - 1.0f);
}
// elu'(z) recovered from h = elu(z):  h>0 -> 1,  else exp(z) = h+1
static __device__ __forceinline__ float elu_d(float h) {
    return (h > 0.0f) ? 1.0f : (h + 1.0f);
}

// ---------------------------------------------------------------------------
// Persistent per-particle kernel: each thread owns one (b, n) particle and
// integrates all nsteps in registers. Weights broadcast from SMEM.
// Shapes fixed by the problem: B=128, N=2048, D=2, row stride 4103.
// ---------------------------------------------------------------------------
__global__ void __launch_bounds__(TB, 1)
phinn_kernel(const float* __restrict__ x,
             const float* __restrict__ W1, const float* __restrict__ b1,
             const float* __restrict__ W2, const float* __restrict__ b2,
             const float* __restrict__ W3, const float* __restrict__ b3,
             const float* __restrict__ W4, const float* __restrict__ b4,
             const float* __restrict__ W5, const float* __restrict__ b5,
             const float* __restrict__ Wt,
             const float* __restrict__ dtp,
             const int*   __restrict__ nstepsp,
             float* __restrict__ out,
             int particles)
{
    __shared__ float sW1[32], sB1[16], sW2[512], sB2[32], sW3[1024], sB3[32],
                     sW4[512], sB4[16], sW5[16], sWt[4];
    __shared__ float sB5;
    __shared__ uint2 skey[512];   // per-step folded keys

    const int tid = threadIdx.x;
    for (int i = tid; i < 32;   i += TB) sW1[i] = W1[i];
    for (int i = tid; i < 16;   i += TB) sB1[i] = b1[i];
    for (int i = tid; i < 512;  i += TB) sW2[i] = W2[i];
    for (int i = tid; i < 32;   i += TB) sB2[i] = b2[i];
    for (int i = tid; i < 1024; i += TB) sW3[i] = W3[i];
    for (int i = tid; i < 32;   i += TB) sB3[i] = b3[i];
    for (int i = tid; i < 512;  i += TB) sW4[i] = W4[i];
    for (int i = tid; i < 16;   i += TB) sB4[i] = b4[i];
    for (int i = tid; i < 16;   i += TB) sW5[i] = W5[i];
    for (int i = tid; i < 4;    i += TB) sWt[i] = Wt[i];
    if (tid == 0) sB5 = b5[0];

    int nsteps = *nstepsp;           // int32 (low word also correct if int64)
    if (nsteps > 512) nsteps = 512;
    if (nsteps < 0)   nsteps = 0;

    // folded key per step: threefry((0,42), (0, s))  == jax.random.fold_in(key(42), s)
    for (int s = tid; s < nsteps; s += TB) {
        uint32_t o0, o1;
        tf2x32(0u, 42u, 0u, (uint32_t)s, o0, o1);
        skey[s] = make_uint2(o0, o1);
    }
    __syncthreads();

    const int p = blockIdx.x * TB + tid;
    if (p >= particles) return;

    const float dtv  = *dtp;
    const float sqdt = sqrtf(dtv);

    const int b = p >> 11;           // N = 2048
    const int n = p & 2047;
    const int xbase = b * 4103;      // 1 + 1 + 4096 + 1 + 4 columns

    float t = x[xbase + 0];
    const float tcrit  = x[xbase + 4098];
    const float spre0  = x[xbase + 4099], spre1  = x[xbase + 4100];
    const float spost0 = x[xbase + 4101], spost1 = x[xbase + 4102];
    const float wt00 = sWt[0], wt01 = sWt[1], wt10 = sWt[2], wt11 = sWt[3];

    float y0v = x[xbase + 2 + 2 * n];
    float y1v = x[xbase + 2 + 2 * n + 1];

    // threefry counter geometry: flat index m in (B, N, D); iota split in half.
    const uint32_t m0   = ((uint32_t)b << 12) + 2u * (uint32_t)n;  // = b*4096 + 2n
    const uint32_t j0   = m0 & 0x3FFFFu;                           // block index (mod 2^18)
    const int      half = (int)(m0 >> 18);                         // which cipher output

    for (int s = 0; s < nsteps; ++s) {
        // ---- noise: 2 cipher blocks, pick output half ----
        const uint2 kk = skey[s];
        uint32_t c0, c1, d0, d1;
        tf2x32(kk.x, kk.y, j0,      j0 + 0x40000u,      c0, c1);
        tf2x32(kk.x, kk.y, j0 + 1u, j0 + 1u + 0x40000u, d0, d1);
        const float n0 = bits_to_normal(half ? c1 : c0);
        const float n1 = bits_to_normal(half ? d1 : d0);

        // ---- forward MLP (activations kept; elu' recoverable from h) ----
        float a1[16], a2[32], a3[32], a4[16];
        #pragma unroll
        for (int o = 0; o < 16; ++o) {
            float z = fmaf(sW1[2*o+1], y1v, fmaf(sW1[2*o], y0v, sB1[o]));
            a1[o] = elu_f(z);
        }
        #pragma unroll
        for (int o = 0; o < 32; ++o) {
            float z = sB2[o];
            #pragma unroll
            for (int i = 0; i < 16; ++i) z = fmaf(sW2[16*o+i], a1[i], z);
            a2[o] = elu_f(z);
        }
        #pragma unroll
        for (int o = 0; o < 32; ++o) {
            float z = sB3[o];
            #pragma unroll
            for (int i = 0; i < 32; ++i) z = fmaf(sW3[32*o+i], a2[i], z);
            a3[o] = elu_f(z);
        }
        #pragma unroll
        for (int o = 0; o < 16; ++o) {
            float z = sB4[o];
            #pragma unroll
            for (int i = 0; i < 32; ++i) z = fmaf(sW4[32*o+i], a3[i], z);
            a4[o] = elu_f(z);
        }
        float z5 = sB5;
        #pragma unroll
        for (int i = 0; i < 16; ++i) z5 = fmaf(sW5[i], a4[i], z5);
        const float g5 = __fdividef(1.0f, 1.0f + __expf(-z5));   // softplus'

        // ---- backward (in-place: a_l becomes g_l) ----
        #pragma unroll
        for (int o = 0; o < 16; ++o)
            a4[o] = sW5[o] * g5 * elu_d(a4[o]);
        #pragma unroll
        for (int i = 0; i < 32; ++i) {
            float acc = 0.0f;
            #pragma unroll
            for (int o = 0; o < 16; ++o) acc = fmaf(sW4[32*o+i], a4[o], acc);
            a3[i] = acc * elu_d(a3[i]);
        }
        #pragma unroll
        for (int i = 0; i < 32; ++i) {
            float acc = 0.0f;
            #pragma unroll
            for (int o = 0; o < 32; ++o) acc = fmaf(sW3[32*o+i], a3[o], acc);
            a2[i] = acc * elu_d(a2[i]);
        }
        #pragma unroll
        for (int i = 0; i < 16; ++i) {
            float acc = 0.0f;
            #pragma unroll
            for (int o = 0; o < 32; ++o) acc = fmaf(sW2[16*o+i], a2[o], acc);
            a1[i] = acc * elu_d(a1[i]);
        }
        float gx = 0.0f, gy = 0.0f;
        #pragma unroll
        for (int o = 0; o < 16; ++o) {
            gx = fmaf(sW1[2*o],   a1[o], gx);
            gy = fmaf(sW1[2*o+1], a1[o], gy);
        }

        // ---- tilt + Euler-Maruyama update (fp32 t accumulation matches scan) ----
        const bool  pre = t < tcrit;
        const float s0v = pre ? spre0 : spost0;
        const float s1v = pre ? spre1 : spost1;
        const float tilt0 = fmaf(wt01, s1v, wt00 * s0v);
        const float tilt1 = fmaf(wt11, s1v, wt10 * s0v);

        const float dr0 = -(gx + tilt0);
        const float dr1 = -(gy + tilt1);

        y0v = fmaf(0.001f, n0 * sqdt, fmaf(dr0, dtv, y0v));
        y1v = fmaf(0.001f, n1 * sqdt, fmaf(dr1, dtv, y1v));

        t += dtv;
    }

    out[m0]      = y0v;
    out[m0 + 1u] = y1v;
}

// ---------------------------------------------------------------------------
extern "C" void kernel_launch(void* const* d_in, const int* in_sizes, int n_in,
                              void* d_out, int out_size) {
    const float* x   = (const float*)d_in[0];
    const float* W1  = (const float*)d_in[1];
    const float* b1  = (const float*)d_in[2];
    const float* W2  = (const float*)d_in[3];
    const float* b2  = (const float*)d_in[4];
    const float* W3  = (const float*)d_in[5];
    const float* b3  = (const float*)d_in[6];
    const float* W4  = (const float*)d_in[7];
    const float* b4  = (const float*)d_in[8];
    const float* W5  = (const float*)d_in[9];
    const float* b5  = (const float*)d_in[10];
    const float* Wt  = (const float*)d_in[11];
    const float* dt  = (const float*)d_in[12];
    const int*   nst = (const int*)d_in[13];

    const int particles = out_size / 2;              // (B*N) = 262144
    const int blocks    = (particles + TB - 1) / TB; // 1024

    phinn_kernel<<<blocks, TB>>>(x, W1, b1, W2, b2, W3, b3, W4, b4, W5, b5,
                                 Wt, dt, nst, (float*)d_out, particles);
}

// round 2
// speedup vs baseline: 11.4089x; 11.4089x over previous
#include <cuda_runtime.h>
#include <stdint.h>
#include <math.h>

#define TB 128
#define KBAR() asm volatile("" ::: "memory")

// ---------------------------------------------------------------------------
// Threefry-2x32, 20 rounds — bit-exact match of jax._src.prng.threefry2x32.
// ---------------------------------------------------------------------------
static __device__ __forceinline__ uint32_t rotl32(uint32_t x, uint32_t r) {
    return __funnelshift_l(x, x, r);
}

static __device__ __forceinline__ void tf2x32(uint32_t k0, uint32_t k1,
                                              uint32_t x0, uint32_t x1,
                                              uint32_t &o0, uint32_t &o1) {
    const uint32_t k2 = k0 ^ k1 ^ 0x1BD11BDAu;
    x0 += k0; x1 += k1;

    x0 += x1; x1 = rotl32(x1, 13); x1 ^= x0;
    x0 += x1; x1 = rotl32(x1, 15); x1 ^= x0;
    x0 += x1; x1 = rotl32(x1, 26); x1 ^= x0;
    x0 += x1; x1 = rotl32(x1,  6); x1 ^= x0;
    x0 += k1; x1 += k2 + 1u;

    x0 += x1; x1 = rotl32(x1, 17); x1 ^= x0;
    x0 += x1; x1 = rotl32(x1, 29); x1 ^= x0;
    x0 += x1; x1 = rotl32(x1, 16); x1 ^= x0;
    x0 += x1; x1 = rotl32(x1, 24); x1 ^= x0;
    x0 += k2; x1 += k0 + 2u;

    x0 += x1; x1 = rotl32(x1, 13); x1 ^= x0;
    x0 += x1; x1 = rotl32(x1, 15); x1 ^= x0;
    x0 += x1; x1 = rotl32(x1, 26); x1 ^= x0;
    x0 += x1; x1 = rotl32(x1,  6); x1 ^= x0;
    x0 += k0; x1 += k1 + 3u;

    x0 += x1; x1 = rotl32(x1, 17); x1 ^= x0;
    x0 += x1; x1 = rotl32(x1, 29); x1 ^= x0;
    x0 += x1; x1 = rotl32(x1, 16); x1 ^= x0;
    x0 += x1; x1 = rotl32(x1, 24); x1 ^= x0;
    x0 += k1; x1 += k2 + 4u;

    x0 += x1; x1 = rotl32(x1, 13); x1 ^= x0;
    x0 += x1; x1 = rotl32(x1, 15); x1 ^= x0;
    x0 += x1; x1 = rotl32(x1, 26); x1 ^= x0;
    x0 += x1; x1 = rotl32(x1,  6); x1 ^= x0;
    o0 = x0 + k2;
    o1 = x1 + k0 + 5u;
}

// bits -> N(0,1), matching jax.random.normal exactly:
// u = uniform over [nextafter(-1,0), 1) via top-23-mantissa trick, then sqrt(2)*erfinv(u).
// mul and add kept un-fused to mirror XLA's separate roundings.
static __device__ __forceinline__ float bits_to_normal(uint32_t bits) {
    float f = __uint_as_float((bits >> 9) | 0x3f800000u) - 1.0f;   // [0,1)
    float u = __fadd_rn(__fmul_rn(f, 2.0f), -0.99999994f);
    u = fmaxf(-0.99999994f, u);
    return 1.41421356237309515f * erfinvf(u);
}

static __device__ __forceinline__ float elu_f(float z) {
    return (z > 0.0f) ? z : (__expf(z) - 1.0f);
}
// elu'(z) recovered from h = elu(z):  h>0 -> 1,  else exp(z) = h+1
static __device__ __forceinline__ float elu_d(float h) {
    return (h > 0.0f) ? 1.0f : (h + 1.0f);
}

// ---------------------------------------------------------------------------
// Persistent per-particle kernel. One thread = one (b, n) particle, all steps
// in registers. Weights (+ transposed copies for backward) broadcast from SMEM
// via float4 loads. B=128, N=2048, D=2, x row stride 4103.
// ---------------------------------------------------------------------------
__global__ void __launch_bounds__(TB)
phinn_kernel(const float* __restrict__ x,
             const float* __restrict__ W1, const float* __restrict__ b1,
             const float* __restrict__ W2, const float* __restrict__ b2,
             const float* __restrict__ W3, const float* __restrict__ b3,
             const float* __restrict__ W4, const float* __restrict__ b4,
             const float* __restrict__ W5, const float* __restrict__ b5,
             const float* __restrict__ Wt,
             const float* __restrict__ dtp,
             const int*   __restrict__ nstepsp,
             float* __restrict__ out,
             int particles)
{
    __shared__ float sW1[32], sB1[16], sB2[32], sB3[32], sB4[16], sWt[4], sB5;
    __shared__ __align__(16) float sW2 [512], sW3 [1024], sW4 [512], sW5[16];
    __shared__ __align__(16) float sW2T[512], sW3T[1024], sW4T[512];
    __shared__ uint2 skey[512];

    const int tid = threadIdx.x;

    for (int i = tid; i < 32;   i += TB) sW1[i] = W1[i];
    for (int i = tid; i < 16;   i += TB) sB1[i] = b1[i];
    for (int i = tid; i < 512;  i += TB) sW2[i] = W2[i];
    for (int i = tid; i < 32;   i += TB) sB2[i] = b2[i];
    for (int i = tid; i < 1024; i += TB) sW3[i] = W3[i];
    for (int i = tid; i < 32;   i += TB) sB3[i] = b3[i];
    for (int i = tid; i < 512;  i += TB) sW4[i] = W4[i];
    for (int i = tid; i < 16;   i += TB) sB4[i] = b4[i];
    for (int i = tid; i < 16;   i += TB) sW5[i] = W5[i];
    for (int i = tid; i < 4;    i += TB) sWt[i] = Wt[i];
    if (tid == 0) sB5 = b5[0];

    // transposed copies: contiguous rows for the backward pass
    for (int i = tid; i < 512; i += TB) {        // W2T[i][o] = W2[o][i]  (16x32)
        int r = i >> 5, o = i & 31;
        sW2T[i] = W2[o * 16 + r];
    }
    for (int i = tid; i < 1024; i += TB) {       // W3T[i][o] = W3[o][i]  (32x32)
        int r = i >> 5, o = i & 31;
        sW3T[i] = W3[o * 32 + r];
    }
    for (int i = tid; i < 512; i += TB) {        // W4T[i][o] = W4[o][i]  (32x16)
        int r = i >> 4, o = i & 15;
        sW4T[i] = W4[o * 32 + r];
    }

    int nsteps = *nstepsp;
    if (nsteps > 512) nsteps = 512;
    if (nsteps < 0)   nsteps = 0;

    // per-step folded keys: threefry((0,42), (0, s)) == fold_in(key(42), s)
    for (int s = tid; s < nsteps; s += TB) {
        uint32_t o0, o1;
        tf2x32(0u, 42u, 0u, (uint32_t)s, o0, o1);
        skey[s] = make_uint2(o0, o1);
    }
    __syncthreads();

    const int p = blockIdx.x * TB + tid;
    if (p >= particles) return;

    const float dtv  = *dtp;
    const float sqdt = sqrtf(dtv);

    const int b = p >> 11;           // N = 2048
    const int n = p & 2047;
    const int xbase = b * 4103;

    float t = x[xbase + 0];
    const float tcrit  = x[xbase + 4098];
    const float spre0  = x[xbase + 4099], spre1  = x[xbase + 4100];
    const float spost0 = x[xbase + 4101], spost1 = x[xbase + 4102];
    const float wt00 = sWt[0], wt01 = sWt[1], wt10 = sWt[2], wt11 = sWt[3];

    float y0v = x[xbase + 2 + 2 * n];
    float y1v = x[xbase + 2 + 2 * n + 1];

    // partitionable threefry: bits[m] = low word of cipher(key, (0, m))
    const uint32_t m0 = ((uint32_t)b << 12) + 2u * (uint32_t)n;

    const float4* W2v  = (const float4*)sW2;
    const float4* W3v  = (const float4*)sW3;
    const float4* W4v  = (const float4*)sW4;
    const float4* W5v  = (const float4*)sW5;
    const float4* W2Tv = (const float4*)sW2T;
    const float4* W3Tv = (const float4*)sW3T;
    const float4* W4Tv = (const float4*)sW4T;

    for (int s = 0; s < nsteps; ++s) {
        // ---------------- forward ----------------
        float a1[16], a2[32], a3[32], a4[16];
        #pragma unroll
        for (int o = 0; o < 16; ++o) {
            float z = fmaf(sW1[2*o+1], y1v, fmaf(sW1[2*o], y0v, sB1[o]));
            a1[o] = elu_f(z);
        }
        KBAR();
        #pragma unroll
        for (int o = 0; o < 32; ++o) {
            float z = sB2[o];
            #pragma unroll
            for (int j = 0; j < 4; ++j) {
                float4 w = W2v[o*4 + j];
                z = fmaf(w.x, a1[4*j+0], z);
                z = fmaf(w.y, a1[4*j+1], z);
                z = fmaf(w.z, a1[4*j+2], z);
                z = fmaf(w.w, a1[4*j+3], z);
            }
            a2[o] = elu_f(z);
        }
        KBAR();
        #pragma unroll
        for (int o = 0; o < 32; ++o) {
            float z = sB3[o];
            #pragma unroll
            for (int j = 0; j < 8; ++j) {
                float4 w = W3v[o*8 + j];
                z = fmaf(w.x, a2[4*j+0], z);
                z = fmaf(w.y, a2[4*j+1], z);
                z = fmaf(w.z, a2[4*j+2], z);
                z = fmaf(w.w, a2[4*j+3], z);
            }
            a3[o] = elu_f(z);
        }
        KBAR();
        #pragma unroll
        for (int o = 0; o < 16; ++o) {
            float z = sB4[o];
            #pragma unroll
            for (int j = 0; j < 8; ++j) {
                float4 w = W4v[o*8 + j];
                z = fmaf(w.x, a3[4*j+0], z);
                z = fmaf(w.y, a3[4*j+1], z);
                z = fmaf(w.z, a3[4*j+2], z);
                z = fmaf(w.w, a3[4*j+3], z);
            }
            a4[o] = elu_f(z);
        }
        KBAR();
        float z5 = sB5;
        #pragma unroll
        for (int j = 0; j < 4; ++j) {
            float4 w = W5v[j];
            z5 = fmaf(w.x, a4[4*j+0], z5);
            z5 = fmaf(w.y, a4[4*j+1], z5);
            z5 = fmaf(w.z, a4[4*j+2], z5);
            z5 = fmaf(w.w, a4[4*j+3], z5);
        }
        const float g5 = __fdividef(1.0f, 1.0f + __expf(-z5));   // softplus'

        // ---------------- backward (in-place a_l -> g_l) ----------------
        #pragma unroll
        for (int o = 0; o < 16; ++o)
            a4[o] = sW5[o] * g5 * elu_d(a4[o]);
        KBAR();
        #pragma unroll
        for (int i = 0; i < 32; ++i) {           // g3 = W4^T g4
            float acc = 0.0f;
            #pragma unroll
            for (int j = 0; j < 4; ++j) {
                float4 w = W4Tv[i*4 + j];
                acc = fmaf(w.x, a4[4*j+0], acc);
                acc = fmaf(w.y, a4[4*j+1], acc);
                acc = fmaf(w.z, a4[4*j+2], acc);
                acc = fmaf(w.w, a4[4*j+3], acc);
            }
            a3[i] = acc * elu_d(a3[i]);
        }
        KBAR();
        #pragma unroll
        for (int i = 0; i < 32; ++i) {           // g2 = W3^T g3
            float acc = 0.0f;
            #pragma unroll
            for (int j = 0; j < 8; ++j) {
                float4 w = W3Tv[i*8 + j];
                acc = fmaf(w.x, a3[4*j+0], acc);
                acc = fmaf(w.y, a3[4*j+1], acc);
                acc = fmaf(w.z, a3[4*j+2], acc);
                acc = fmaf(w.w, a3[4*j+3], acc);
            }
            a2[i] = acc * elu_d(a2[i]);
        }
        KBAR();
        #pragma unroll
        for (int i = 0; i < 16; ++i) {           // g1 = W2^T g2
            float acc = 0.0f;
            #pragma unroll
            for (int j = 0; j < 8; ++j) {
                float4 w = W2Tv[i*8 + j];
                acc = fmaf(w.x, a2[4*j+0], acc);
                acc = fmaf(w.y, a2[4*j+1], acc);
                acc = fmaf(w.z, a2[4*j+2], acc);
                acc = fmaf(w.w, a2[4*j+3], acc);
            }
            a1[i] = acc * elu_d(a1[i]);
        }
        KBAR();
        float gx = 0.0f, gy = 0.0f;
        #pragma unroll
        for (int o = 0; o < 16; ++o) {
            gx = fmaf(sW1[2*o],   a1[o], gx);
            gy = fmaf(sW1[2*o+1], a1[o], gy);
        }
        KBAR();

        // ---------------- noise (partitionable threefry) ----------------
        const uint2 kk = skey[s];
        uint32_t c0, c1, d0, d1;
        tf2x32(kk.x, kk.y, 0u, m0,      c0, c1);
        tf2x32(kk.x, kk.y, 0u, m0 + 1u, d0, d1);
        const float n0 = bits_to_normal(c1);     // low word of 64-bit output
        const float n1 = bits_to_normal(d1);

        // ---------------- tilt + Euler–Maruyama ----------------
        const bool  pre = t < tcrit;
        const float s0v = pre ? spre0 : spost0;
        const float s1v = pre ? spre1 : spost1;
        const float tilt0 = fmaf(wt01, s1v, wt00 * s0v);
        const float tilt1 = fmaf(wt11, s1v, wt10 * s0v);

        const float dr0 = -(gx + tilt0);
        const float dr1 = -(gy + tilt1);

        y0v = fmaf(0.001f, n0 * sqdt, fmaf(dr0, dtv, y0v));
        y1v = fmaf(0.001f, n1 * sqdt, fmaf(dr1, dtv, y1v));

        t += dtv;
    }

    out[m0]      = y0v;
    out[m0 + 1u] = y1v;
}

// ---------------------------------------------------------------------------
extern "C" void kernel_launch(void* const* d_in, const int* in_sizes, int n_in,
                              void* d_out, int out_size) {
    const float* x   = (const float*)d_in[0];
    const float* W1  = (const float*)d_in[1];
    const float* b1  = (const float*)d_in[2];
    const float* W2  = (const float*)d_in[3];
    const float* b2  = (const float*)d_in[4];
    const float* W3  = (const float*)d_in[5];
    const float* b3  = (const float*)d_in[6];
    const float* W4  = (const float*)d_in[7];
    const float* b4  = (const float*)d_in[8];
    const float* W5  = (const float*)d_in[9];
    const float* b5  = (const float*)d_in[10];
    const float* Wt  = (const float*)d_in[11];
    const float* dt  = (const float*)d_in[12];
    const int*   nst = (const int*)d_in[13];

    const int particles = out_size / 2;              // B*N = 262144
    const int blocks    = (particles + TB - 1) / TB; // 2048

    phinn_kernel<<<blocks, TB>>>(x, W1, b1, W2, b2, W3, b3, W4, b4, W5, b5,
                                 Wt, dt, nst, (float*)d_out, particles);
}